// round 1
// baseline (speedup 1.0000x reference)
#include <cuda_runtime.h>
#include <math.h>

#define B_ 64
#define S_ 2048
#define D_ 512

// Scratch (static device globals — no runtime allocation allowed)
__device__ float g_dec_part[B_ * D_];
__device__ float g_score[B_ * S_];

// ---------------------------------------------------------------------------
// Kernel 1: dec_part[b][d] = b_t[d] + sum_e dec[b][e] * W_t[e][d]
// (first D rows of W_t act on the broadcast decoder vector — batch-only work)
// ---------------------------------------------------------------------------
__global__ void decpart_kernel(const float* __restrict__ dec,
                               const float* __restrict__ Wt,
                               const float* __restrict__ bt) {
    int b = blockIdx.x;
    int d = threadIdx.x;  // 512 threads
    __shared__ float ds[D_];
    ds[d] = dec[b * D_ + d];
    __syncthreads();
    float acc = bt[d];
#pragma unroll 8
    for (int e = 0; e < D_; e++)
        acc = fmaf(ds[e], Wt[(size_t)e * D_ + d], acc);
    g_dec_part[b * D_ + d] = acc;
}

// ---------------------------------------------------------------------------
// Kernel 2: score[b][s] = sum_d tanh( (enc[b,s,:] @ Wenc)[d] + dec_part[b][d] ) * v_a[d]
// Tiled fp32 GEMM: block = 128 s-rows, loops all 4 n-chunks of 128 d-cols,
// K=512 in 16-wide shared tiles, 8x8 register micro-tile per thread.
// Row-score reduced over tx via shfl, written directly (no atomics).
// ---------------------------------------------------------------------------
#define TM 128
#define TN 128
#define TK 16

__global__ __launch_bounds__(256, 2)
void score_kernel(const float* __restrict__ enc,
                  const float* __restrict__ Wt,
                  const float* __restrict__ va) {
    int b  = blockIdx.y;
    int s0 = blockIdx.x * TM;
    int tid = threadIdx.x;          // 256 threads
    int tx = tid & 15;              // n dimension (16)
    int ty = tid >> 4;              // m dimension (16)

    __shared__ float As[TK][TM];    // enc tile, transposed: [k][m]
    __shared__ float Bs[TK][TN];    // W_enc tile: [k][n]

    const float* encB = enc + ((size_t)b * S_ + s0) * D_;
    const float* Wenc = Wt + (size_t)D_ * D_;   // rows D..2D-1 of W_t

    float row_score[8];
#pragma unroll
    for (int i = 0; i < 8; i++) row_score[i] = 0.f;

    for (int nc = 0; nc < D_ / TN; nc++) {
        int n0 = nc * TN;
        float acc[8][8];
#pragma unroll
        for (int i = 0; i < 8; i++)
#pragma unroll
            for (int j = 0; j < 8; j++) acc[i][j] = 0.f;

        for (int k0 = 0; k0 < D_; k0 += TK) {
            // Load enc tile (128 x 16), store transposed into As[k][m]
#pragma unroll
            for (int l = 0; l < 2; l++) {
                int idx = tid + l * 256;        // 0..511  (512 float4 loads)
                int r  = idx >> 2;              // s-row 0..127
                int c4 = (idx & 3) * 4;         // k offset 0,4,8,12
                float4 v = *reinterpret_cast<const float4*>(
                    encB + (size_t)r * D_ + k0 + c4);
                As[c4 + 0][r] = v.x;
                As[c4 + 1][r] = v.y;
                As[c4 + 2][r] = v.z;
                As[c4 + 3][r] = v.w;
            }
            // Load W_enc tile (16 x 128), row-major match
#pragma unroll
            for (int l = 0; l < 2; l++) {
                int idx = tid + l * 256;
                int r  = idx >> 5;              // k row 0..15
                int c4 = (idx & 31) * 4;        // n offset
                *reinterpret_cast<float4*>(&Bs[r][c4]) =
                    *reinterpret_cast<const float4*>(
                        Wenc + (size_t)(k0 + r) * D_ + n0 + c4);
            }
            __syncthreads();

#pragma unroll
            for (int k = 0; k < TK; k++) {
                float a[8], w[8];
#pragma unroll
                for (int i = 0; i < 8; i++) a[i] = As[k][ty * 8 + i];
#pragma unroll
                for (int j = 0; j < 8; j++) w[j] = Bs[k][tx * 8 + j];
#pragma unroll
                for (int i = 0; i < 8; i++)
#pragma unroll
                    for (int j = 0; j < 8; j++)
                        acc[i][j] = fmaf(a[i], w[j], acc[i][j]);
            }
            __syncthreads();
        }

        // Epilogue for this n-chunk: tanh + dot with v_a
        float vr[8], dp[8];
#pragma unroll
        for (int j = 0; j < 8; j++) {
            vr[j] = va[n0 + tx * 8 + j];
            dp[j] = g_dec_part[b * D_ + n0 + tx * 8 + j];
        }
#pragma unroll
        for (int i = 0; i < 8; i++) {
            float s = 0.f;
#pragma unroll
            for (int j = 0; j < 8; j++)
                s += tanhf(acc[i][j] + dp[j]) * vr[j];
            row_score[i] += s;
        }
    }

    // Reduce partial row scores across tx (lane bits 0..3)
#pragma unroll
    for (int off = 8; off > 0; off >>= 1)
#pragma unroll
        for (int i = 0; i < 8; i++)
            row_score[i] += __shfl_xor_sync(0xffffffffu, row_score[i], off);

    if (tx == 0) {
#pragma unroll
        for (int i = 0; i < 8; i++)
            g_score[b * S_ + s0 + ty * 8 + i] = row_score[i];
    }
}

// ---------------------------------------------------------------------------
// Kernel 3: per-batch softmax over S scores + context = alpha @ enc
// out layout: [0, B*D) = context_vector, [B*D, B*D + B*S) = alignment
// (b_v dropped: softmax is shift-invariant)
// ---------------------------------------------------------------------------
__global__ void softmax_ctx_kernel(const float* __restrict__ enc,
                                   float* __restrict__ out) {
    int b = blockIdx.x;
    int t = threadIdx.x;            // 512 threads
    __shared__ float sa[S_];
    __shared__ float red[16];

    float v[4];
    float m = -1e30f;
#pragma unroll
    for (int i = 0; i < 4; i++) {
        v[i] = g_score[b * S_ + t + i * 512];
        m = fmaxf(m, v[i]);
    }
    // block max
    for (int off = 16; off > 0; off >>= 1)
        m = fmaxf(m, __shfl_xor_sync(0xffffffffu, m, off));
    if ((t & 31) == 0) red[t >> 5] = m;
    __syncthreads();
    if (t < 16) {
        float mm = red[t];
        for (int off = 8; off > 0; off >>= 1)
            mm = fmaxf(mm, __shfl_xor_sync(0xffffu, mm, off));
        red[t] = mm;
    }
    __syncthreads();
    m = red[0];
    __syncthreads();

    float sum = 0.f;
#pragma unroll
    for (int i = 0; i < 4; i++) {
        float e = expf(v[i] - m);
        sa[t + i * 512] = e;
        sum += e;
    }
    for (int off = 16; off > 0; off >>= 1)
        sum += __shfl_xor_sync(0xffffffffu, sum, off);
    if ((t & 31) == 0) red[t >> 5] = sum;
    __syncthreads();
    if (t < 16) {
        float ss = red[t];
        for (int off = 8; off > 0; off >>= 1)
            ss += __shfl_xor_sync(0xffffu, ss, off);
        red[t] = ss;
    }
    __syncthreads();
    float inv = 1.f / red[0];

    // alignment output
#pragma unroll
    for (int i = 0; i < 4; i++)
        out[B_ * D_ + b * S_ + t + i * 512] = sa[t + i * 512] * inv;

    // context: thread t owns output column d = t
    float acc = 0.f;
    const float* eb = enc + (size_t)b * S_ * D_ + t;
#pragma unroll 8
    for (int s = 0; s < S_; s++)
        acc = fmaf(sa[s], eb[(size_t)s * D_], acc);
    out[b * D_ + t] = acc * inv;
}

// ---------------------------------------------------------------------------
// Launch
// Inputs (metadata order): decoder_output, encoder_output, W_t, b_t, v_a, b_v
// ---------------------------------------------------------------------------
extern "C" void kernel_launch(void* const* d_in, const int* in_sizes, int n_in,
                              void* d_out, int out_size) {
    const float* dec = (const float*)d_in[0];
    const float* enc = (const float*)d_in[1];
    const float* Wt  = (const float*)d_in[2];
    const float* bt  = (const float*)d_in[3];
    const float* va  = (const float*)d_in[4];
    // d_in[5] = b_v, unused (softmax shift invariance)
    float* out = (float*)d_out;

    decpart_kernel<<<B_, D_>>>(dec, Wt, bt);

    dim3 grid(S_ / TM, B_);
    score_kernel<<<grid, 256>>>(enc, Wt, va);

    softmax_ctx_kernel<<<B_, 512>>>(enc, out);
}

// round 3
// speedup vs baseline: 2.5484x; 2.5484x over previous
#include <cuda_runtime.h>
#include <cuda_bf16.h>
#include <math.h>
#include <stdint.h>

#define B_ 64
#define S_ 2048
#define D_ 512

// ---------------- scratch (static device globals) ----------------
__device__ float g_dec_part[B_ * D_];
__device__ float g_score[B_ * S_];
__device__ __align__(16) __nv_bfloat16 g_WhiT[D_ * D_];  // W_enc^T hi, [n][k]
__device__ __align__(16) __nv_bfloat16 g_WloT[D_ * D_];  // W_enc^T lo
__device__ float g_ctx_part[8 * B_ * D_];

// ---------------- helpers ----------------
__device__ __forceinline__ uint32_t smem_u32(const void* p) {
    uint32_t a;
    asm("{ .reg .u64 t; cvta.to.shared.u64 t, %1; cvt.u32.u64 %0, t; }"
        : "=r"(a) : "l"(p));
    return a;
}

__device__ __forceinline__ void ldsm4(uint32_t* r, uint32_t addr) {
    asm volatile("ldmatrix.sync.aligned.m8n8.x4.shared.b16 {%0,%1,%2,%3}, [%4];"
                 : "=r"(r[0]), "=r"(r[1]), "=r"(r[2]), "=r"(r[3]) : "r"(addr));
}

__device__ __forceinline__ void mma16816(float* c, const uint32_t* a,
                                         const uint32_t* b) {
    asm volatile(
        "mma.sync.aligned.m16n8k16.row.col.f32.bf16.bf16.f32 "
        "{%0,%1,%2,%3}, {%4,%5,%6,%7}, {%8,%9}, {%0,%1,%2,%3};"
        : "+f"(c[0]), "+f"(c[1]), "+f"(c[2]), "+f"(c[3])
        : "r"(a[0]), "r"(a[1]), "r"(a[2]), "r"(a[3]), "r"(b[0]), "r"(b[1]));
}

__device__ __forceinline__ uint32_t pack_bf2(__nv_bfloat16 a, __nv_bfloat16 b) {
    __nv_bfloat162 t = __halves2bfloat162(a, b);
    return *reinterpret_cast<uint32_t*>(&t);
}

// ---------------------------------------------------------------------------
// Kernel 1: dec_part[b][d] = b_t[d] + dec[b] @ W_t[:D]
// ---------------------------------------------------------------------------
__global__ void decpart_kernel(const float* __restrict__ dec,
                               const float* __restrict__ Wt,
                               const float* __restrict__ bt) {
    __shared__ float ds[D_];
    int b = blockIdx.y;
    int d = blockIdx.x * 128 + threadIdx.x;
    for (int i = threadIdx.x; i < D_; i += 128) ds[i] = dec[b * D_ + i];
    __syncthreads();
    float acc = bt[d];
#pragma unroll 8
    for (int e = 0; e < D_; e++)
        acc = fmaf(ds[e], Wt[(size_t)e * D_ + d], acc);
    g_dec_part[b * D_ + d] = acc;
}

// ---------------------------------------------------------------------------
// Kernel 2: split W_enc -> bf16 hi/lo, transposed to [n][k]
// ---------------------------------------------------------------------------
__global__ void wconv_kernel(const float* __restrict__ Wt) {
    int idx = blockIdx.x * 512 + threadIdx.x;  // idx = k*512 + n
    int k = idx >> 9;
    int n = idx & 511;
    float w = Wt[(size_t)(D_ + k) * D_ + n];
    __nv_bfloat16 hi = __float2bfloat16(w);
    __nv_bfloat16 lo = __float2bfloat16(w - __bfloat162float(hi));
    g_WhiT[(size_t)n * D_ + k] = hi;
    g_WloT[(size_t)n * D_ + k] = lo;
}

// ---------------------------------------------------------------------------
// Kernel 3: score GEMM via mma.sync bf16 3-term split.
// CTA: M=128 s-rows x N=512 (4 chunks of 128) x K=512 (16 chunks of 32).
// 8 warps = 2(m) x 4(n); warp tile 64x32 -> acc[4][4][4].
// Smem rows padded to 80B: ldmatrix conflict-free (20r mod 32 disjoint).
// Epilogue: score[s] = sum_d tanh(acc + dec_part[d]) * v_a[d]
// ---------------------------------------------------------------------------
#define STRIDE 80      // bytes per 32-element bf16 row (64B data + 16B pad)
#define HALF_OFF 10240 // hi->lo offset inside sA / sB

__global__ __launch_bounds__(256, 2)
void score_kernel(const float* __restrict__ enc,
                  const float* __restrict__ va) {
    __shared__ __align__(16) char sA[2 * HALF_OFF];   // A hi | A lo
    __shared__ __align__(16) char sB[2 * HALF_OFF];   // B hi | B lo
    __shared__ float sDec[D_];
    __shared__ float sVa[D_];
    __shared__ float sRed[4 * 128];

    int tid = threadIdx.x;
    int l = tid & 31;
    int w = tid >> 5;
    int warpm = w >> 2;    // 0..1
    int warpn = w & 3;     // 0..3
    int b  = blockIdx.y;
    int s0 = blockIdx.x * 128;

    // stage dec_part + v_a
    sDec[tid]       = g_dec_part[b * D_ + tid];
    sDec[tid + 256] = g_dec_part[b * D_ + tid + 256];
    sVa[tid]        = va[tid];
    sVa[tid + 256]  = va[tid + 256];

    const float* encB = enc + ((size_t)b * S_ + s0) * D_;

    uint32_t sAu = smem_u32(sA);
    uint32_t sBu = smem_u32(sB);
    // per-lane ldmatrix base offsets
    uint32_t aBase = sAu + warpm * (64 * STRIDE)
                   + (l & 15) * STRIDE + (l >> 4) * 16;
    uint32_t bBase = sBu + warpn * (32 * STRIDE)
                   + ((l & 7) + ((l & 16) >> 1)) * STRIDE + (l & 8) * 2;

    float rp[8];
#pragma unroll
    for (int i = 0; i < 8; i++) rp[i] = 0.f;

    for (int nc = 0; nc < 4; nc++) {
        float acc[4][4][4];
#pragma unroll
        for (int mf = 0; mf < 4; mf++)
#pragma unroll
            for (int nf = 0; nf < 4; nf++)
#pragma unroll
                for (int r = 0; r < 4; r++) acc[mf][nf][r] = 0.f;

        for (int kc = 0; kc < 16; kc++) {
            int k0 = kc * 32;
            __syncthreads();   // previous iteration's reads complete
            // ---- A: 128 rows x 32 k, fp32 -> bf16 hi/lo ----
#pragma unroll
            for (int i = 0; i < 4; i++) {
                int idx = tid + i * 256;       // 0..1023
                int r  = idx >> 3;
                int c4 = (idx & 7) * 4;
                float4 v = *reinterpret_cast<const float4*>(
                    encB + (size_t)r * D_ + k0 + c4);
                float f[4] = {v.x, v.y, v.z, v.w};
                __nv_bfloat16 h[4], lo[4];
#pragma unroll
                for (int j = 0; j < 4; j++) {
                    h[j]  = __float2bfloat16(f[j]);
                    lo[j] = __float2bfloat16(f[j] - __bfloat162float(h[j]));
                }
                uint32_t off = r * STRIDE + c4 * 2;
                uint2 ph = make_uint2(pack_bf2(h[0], h[1]),  pack_bf2(h[2], h[3]));
                uint2 pl = make_uint2(pack_bf2(lo[0], lo[1]), pack_bf2(lo[2], lo[3]));
                *reinterpret_cast<uint2*>(sA + off)            = ph;
                *reinterpret_cast<uint2*>(sA + HALF_OFF + off) = pl;
            }
            // ---- B: 128 n-rows x 32 k bf16 hi/lo ----
#pragma unroll
            for (int i = 0; i < 2; i++) {
                int idx = tid + i * 256;       // 0..511
                int n  = idx >> 2;
                int c8 = (idx & 3) * 8;
                size_t gsrc = (size_t)(nc * 128 + n) * D_ + k0 + c8;
                uint32_t off = n * STRIDE + c8 * 2;
                *reinterpret_cast<float4*>(sB + off) =
                    *reinterpret_cast<const float4*>(&g_WhiT[gsrc]);
                *reinterpret_cast<float4*>(sB + HALF_OFF + off) =
                    *reinterpret_cast<const float4*>(&g_WloT[gsrc]);
            }
            __syncthreads();

            // ---- 2 x k16 MMA steps ----
#pragma unroll
            for (int ks = 0; ks < 2; ks++) {
                uint32_t kby = ks * 32;
                uint32_t a_hi[4][4], a_lo[4][4], b_hi[2][4], b_lo[2][4];
#pragma unroll
                for (int mf = 0; mf < 4; mf++) {
                    uint32_t ad = aBase + mf * (16 * STRIDE) + kby;
                    ldsm4(a_hi[mf], ad);
                    ldsm4(a_lo[mf], ad + HALF_OFF);
                }
#pragma unroll
                for (int bp = 0; bp < 2; bp++)
                    ldsm4(b_hi[bp], bBase + bp * (16 * STRIDE) + kby);
#pragma unroll
                for (int mf = 0; mf < 4; mf++)
#pragma unroll
                    for (int nf = 0; nf < 4; nf++) {
                        const uint32_t* bb = &b_hi[nf >> 1][(nf & 1) * 2];
                        mma16816(acc[mf][nf], a_hi[mf], bb);
                        mma16816(acc[mf][nf], a_lo[mf], bb);
                    }
#pragma unroll
                for (int bp = 0; bp < 2; bp++)
                    ldsm4(b_lo[bp], bBase + HALF_OFF + bp * (16 * STRIDE) + kby);
#pragma unroll
                for (int mf = 0; mf < 4; mf++)
#pragma unroll
                    for (int nf = 0; nf < 4; nf++)
                        mma16816(acc[mf][nf], a_hi[mf],
                                 &b_lo[nf >> 1][(nf & 1) * 2]);
            }
        }

        // ---- epilogue for this n-chunk: tanh + dot v_a ----
        int g = l >> 2, tig = l & 3;
#pragma unroll
        for (int mf = 0; mf < 4; mf++)
#pragma unroll
            for (int nf = 0; nf < 4; nf++)
#pragma unroll
                for (int r = 0; r < 4; r++) {
                    int d = nc * 128 + warpn * 32 + nf * 8 + tig * 2 + (r & 1);
                    float x = acc[mf][nf][r] + sDec[d];
                    // tanh(x) = 1 - 2/(e^{2x}+1)
                    float t = 1.0f - __fdividef(2.0f, __expf(2.0f * x) + 1.0f);
                    rp[mf * 2 + (r >> 1)] += t * sVa[d];
                }
    }

    // reduce over the 4 lanes sharing a row (tig bits)
#pragma unroll
    for (int i = 0; i < 8; i++) {
        rp[i] += __shfl_xor_sync(0xffffffffu, rp[i], 1);
        rp[i] += __shfl_xor_sync(0xffffffffu, rp[i], 2);
    }
    if ((l & 3) == 0) {
        int g = l >> 2;
#pragma unroll
        for (int mf = 0; mf < 4; mf++)
#pragma unroll
            for (int h = 0; h < 2; h++) {
                int row = warpm * 64 + mf * 16 + h * 8 + g;
                sRed[warpn * 128 + row] = rp[mf * 2 + h];
            }
    }
    __syncthreads();
    if (tid < 128)
        g_score[b * S_ + s0 + tid] =
            sRed[tid] + sRed[128 + tid] + sRed[256 + tid] + sRed[384 + tid];
}

// ---------------------------------------------------------------------------
// Kernel 4: per-batch softmax -> alignment
// ---------------------------------------------------------------------------
__global__ void softmax_kernel(float* __restrict__ out) {
    int b = blockIdx.x;
    int t = threadIdx.x;                 // 512 threads
    __shared__ float red[16];

    float v[4];
    float mx = -1e30f;
#pragma unroll
    for (int i = 0; i < 4; i++) {
        v[i] = g_score[b * S_ + t + i * 512];
        mx = fmaxf(mx, v[i]);
    }
    for (int off = 16; off > 0; off >>= 1)
        mx = fmaxf(mx, __shfl_xor_sync(0xffffffffu, mx, off));
    if ((t & 31) == 0) red[t >> 5] = mx;
    __syncthreads();
    if (t < 16) {
        float mm = red[t];
        for (int off = 8; off > 0; off >>= 1)
            mm = fmaxf(mm, __shfl_xor_sync(0xffffu, mm, off));
        red[t] = mm;
    }
    __syncthreads();
    mx = red[0];
    __syncthreads();

    float e[4], sum = 0.f;
#pragma unroll
    for (int i = 0; i < 4; i++) {
        e[i] = expf(v[i] - mx);
        sum += e[i];
    }
    for (int off = 16; off > 0; off >>= 1)
        sum += __shfl_xor_sync(0xffffffffu, sum, off);
    if ((t & 31) == 0) red[t >> 5] = sum;
    __syncthreads();
    if (t < 16) {
        float ss = red[t];
        for (int off = 8; off > 0; off >>= 1)
            ss += __shfl_xor_sync(0xffffu, ss, off);
        red[t] = ss;
    }
    __syncthreads();
    float inv = 1.f / red[0];
#pragma unroll
    for (int i = 0; i < 4; i++)
        out[B_ * D_ + b * S_ + t + i * 512] = e[i] * inv;
}

// ---------------------------------------------------------------------------
// Kernel 5: partial context over 256-row s-chunks
// ---------------------------------------------------------------------------
__global__ void ctx_part_kernel(const float* __restrict__ enc,
                                const float* __restrict__ out_alpha) {
    int sc = blockIdx.x;
    int b  = blockIdx.y;
    int t  = threadIdx.x;                // 512
    __shared__ float as_[256];
    if (t < 256) as_[t] = out_alpha[B_ * D_ + b * S_ + sc * 256 + t];
    __syncthreads();
    float acc = 0.f;
    const float* eb = enc + ((size_t)b * S_ + sc * 256) * D_ + t;
#pragma unroll 8
    for (int s = 0; s < 256; s++)
        acc = fmaf(as_[s], eb[(size_t)s * D_], acc);
    g_ctx_part[(sc * B_ + b) * D_ + t] = acc;
}

// ---------------------------------------------------------------------------
// Kernel 6: combine partials (fixed order -> deterministic)
// ---------------------------------------------------------------------------
__global__ void ctx_combine_kernel(float* __restrict__ out) {
    int b = blockIdx.x;
    int t = threadIdx.x;
    float s = 0.f;
#pragma unroll
    for (int sc = 0; sc < 8; sc++)
        s += g_ctx_part[(sc * B_ + b) * D_ + t];
    out[b * D_ + t] = s;
}

// ---------------------------------------------------------------------------
// Launch. Inputs: decoder_output, encoder_output, W_t, b_t, v_a, b_v(unused)
// out: [0, B*D) context, [B*D, B*D+B*S) alignment
// ---------------------------------------------------------------------------
extern "C" void kernel_launch(void* const* d_in, const int* in_sizes, int n_in,
                              void* d_out, int out_size) {
    const float* dec = (const float*)d_in[0];
    const float* enc = (const float*)d_in[1];
    const float* Wt  = (const float*)d_in[2];
    const float* bt  = (const float*)d_in[3];
    const float* va  = (const float*)d_in[4];
    float* out = (float*)d_out;

    decpart_kernel<<<dim3(4, B_), 128>>>(dec, Wt, bt);
    wconv_kernel<<<512, 512>>>(Wt);
    score_kernel<<<dim3(16, B_), 256>>>(enc, va);
    softmax_kernel<<<B_, 512>>>(out);
    ctx_part_kernel<<<dim3(8, B_), 512>>>(enc, out);
    ctx_combine_kernel<<<B_, 512>>>(out);
}